// round 15
// baseline (speedup 1.0000x reference)
#include <cuda_runtime.h>
#include <cuda_fp16.h>

#define D      128
#define D4     32
#define DH2    32
#define KHOPS  10
#define BM     32

static const int NMAX = 50000;
static const int EMAX = 625000;
static const int SBMAX = 256;           // max scan blocks (ceil(50000/1024)=49)

// ---------------- scratch (device globals; no allocation allowed) ----------
__device__ __half g_bufA[NMAX * D];     // h ping (fp16 state)
__device__ __half g_bufB[NMAX * D];     // h pong
__device__ int    g_deg[NMAX];
__device__ int    g_rowptr[NMAX + 1];
__device__ int    g_cursor[NMAX];
__device__ float  g_dinv[NMAX];
__device__ int2   g_csr[EMAX];          // {src, bitcast(dinv[src])}
__device__ float  g_coeff[KHOPS + 1];
__device__ int    g_is64;
__device__ int    g_bsum[SBMAX];
__device__ unsigned          g_bar_count;
__device__ volatile unsigned g_bar_gen;

// ---------------- software grid barrier (small grids only) ------------------
__device__ __forceinline__ void gridbar() {
    __syncthreads();
    if (threadIdx.x == 0) {
        __threadfence();
        unsigned gen = g_bar_gen;
        if (atomicAdd(&g_bar_count, 1u) == gridDim.x - 1) {
            g_bar_count = 0;
            __threadfence();
            g_bar_gen = gen + 1;
        } else {
            while (g_bar_gen == gen) __nanosleep(32);
        }
        __threadfence();
    }
    __syncthreads();
}

__device__ __forceinline__ int load_idx(const void* ei, long long pos) {
    if (g_is64) return (int)((const long long*)ei)[pos];
    return ((const int*)ei)[pos];
}

// ------------- fp16 helpers --------------------------------------------------
__device__ __forceinline__ void fma_h4(uint2 p, float w, float4& a) {
    float2 lo = __half22float2(*(const __half2*)&p.x);
    float2 hi = __half22float2(*(const __half2*)&p.y);
    a.x = fmaf(w, lo.x, a.x); a.y = fmaf(w, lo.y, a.y);
    a.z = fmaf(w, hi.x, a.z); a.w = fmaf(w, hi.y, a.w);
}
__device__ __forceinline__ uint2 pack_h4(float4 r) {
    __half2 lo = __floats2half2_rn(r.x, r.y);
    __half2 hi = __floats2half2_rn(r.z, r.w);
    uint2 p;
    p.x = *(const unsigned int*)&lo;
    p.y = *(const unsigned int*)&hi;
    return p;
}
__device__ __forceinline__ unsigned int smem_u32(const void* p) {
    return (unsigned int)__cvta_generic_to_shared(p);
}

// ================= LAUNCH 1: tiny pre-pass ==================================
// zero deg + coeffs + dtype detect (W conversion now inline in the GEMM)
__global__ void k_pre(const void* __restrict__ ei,
                      const float* __restrict__ t_ptr, int n) {
    int i = blockIdx.x * blockDim.x + threadIdx.x;
    if (i < n) g_deg[i] = 0;
    if (i == 0) {
        const int* a = (const int*)ei;
        int is64 = 1;
#pragma unroll
        for (int j = 1; j < 32; j += 2)
            if (a[j] != 0) is64 = 0;
        g_is64 = is64;
        float t = *t_ptr;
        float cc = expf(-t);
        g_coeff[0] = cc;
        for (int k = 1; k <= KHOPS; ++k) { cc = cc * t / (float)k; g_coeff[k] = cc; }
    }
}

// ================= LAUNCH 2: combo — GEMM blocks + histogram blocks =========
// blocks [0, ngemm)           : HMMA GEMM tile per block (W converted inline)
// blocks [ngemm, ngemm+nhist) : degree histogram, grid-stride over E
__global__ void __launch_bounds__(256) k_combo(
    const float* __restrict__ x, const float* __restrict__ W,
    const float* __restrict__ b, const void* __restrict__ ei,
    float* __restrict__ out, int n, int E, int ngemm, int nhist)
{
    __shared__ __align__(16) __half sA[BM][D + 8];
    __shared__ __align__(16) __half sW[D][D + 8];

    int tid = threadIdx.x;

    if (blockIdx.x >= (unsigned)ngemm) {
        // -------- histogram part --------
        int gt   = (blockIdx.x - ngemm) * 256 + tid;
        int step = nhist * 256;
        for (int e = gt; e < E; e += step) {
            int dst = load_idx(ei, (long long)E + e);
            atomicAdd(&g_deg[dst], 1);
        }
        return;
    }

    // -------- GEMM part --------
    int warp = tid >> 5;
    int lane = tid & 31;
    int rowb = blockIdx.x * BM;
    int rows = n - rowb; if (rows > BM) rows = BM;

    // W fp32 -> fp16 smem, inline (row = 32 float4s)
    const float4* W4 = (const float4*)W;
#pragma unroll
    for (int i = tid; i < D * D / 4; i += 256) {
        float4 v = W4[i];
        int r = i >> 5, c = (i & 31) * 4;
        *(half2*)&sW[r][c]     = __floats2half2_rn(v.x, v.y);
        *(half2*)&sW[r][c + 2] = __floats2half2_rn(v.z, v.w);
    }
    const float4* x4 = (const float4*)(x + (long long)rowb * D);
    for (int i = tid; i < rows * D4; i += 256) {
        int r = i >> 5, c = i & 31;
        float4 v = x4[i];
        *(half2*)&sA[r][c * 4]     = __floats2half2_rn(v.x, v.y);
        *(half2*)&sA[r][c * 4 + 2] = __floats2half2_rn(v.z, v.w);
    }
    __syncthreads();

    int rg = warp & 1, cg = warp >> 1;
    int r0 = rg * 16;

    float acc[4][4];
#pragma unroll
    for (int j = 0; j < 4; ++j)
#pragma unroll
        for (int q = 0; q < 4; ++q) acc[j][q] = 0.f;

    int aRow = r0 + (lane & 15);
    int aCol = (lane >> 4) << 3;
    int bN = (lane & 7) + ((lane >> 4) << 3);
    int bK = ((lane >> 3) & 1) << 3;

#pragma unroll
    for (int k0 = 0; k0 < D; k0 += 16) {
        unsigned int a0, a1, a2, a3;
        unsigned int aAddr = smem_u32(&sA[aRow][k0 + aCol]);
        asm volatile("ldmatrix.sync.aligned.m8n8.x4.shared.b16 {%0,%1,%2,%3}, [%4];"
                     : "=r"(a0), "=r"(a1), "=r"(a2), "=r"(a3) : "r"(aAddr));
#pragma unroll
        for (int h16 = 0; h16 < 2; ++h16) {
            int nbase = cg * 32 + h16 * 16;
            unsigned int b0, b1, b2, b3;
            unsigned int bAddr = smem_u32(&sW[nbase + bN][k0 + bK]);
            asm volatile("ldmatrix.sync.aligned.m8n8.x4.shared.b16 {%0,%1,%2,%3}, [%4];"
                         : "=r"(b0), "=r"(b1), "=r"(b2), "=r"(b3) : "r"(bAddr));
            int j0 = h16 * 2;
            asm volatile("mma.sync.aligned.m16n8k16.row.col.f32.f16.f16.f32 "
                         "{%0,%1,%2,%3},{%4,%5,%6,%7},{%8,%9},{%0,%1,%2,%3};"
                         : "+f"(acc[j0][0]), "+f"(acc[j0][1]), "+f"(acc[j0][2]), "+f"(acc[j0][3])
                         : "r"(a0), "r"(a1), "r"(a2), "r"(a3), "r"(b0), "r"(b1));
            asm volatile("mma.sync.aligned.m16n8k16.row.col.f32.f16.f16.f32 "
                         "{%0,%1,%2,%3},{%4,%5,%6,%7},{%8,%9},{%0,%1,%2,%3};"
                         : "+f"(acc[j0+1][0]), "+f"(acc[j0+1][1]), "+f"(acc[j0+1][2]), "+f"(acc[j0+1][3])
                         : "r"(a0), "r"(a1), "r"(a2), "r"(a3), "r"(b2), "r"(b3));
        }
    }

    float c0 = g_coeff[0];
    int mlo = rowb + r0 + (lane >> 2);
    int mhi = mlo + 8;
    __half2* h0 = (__half2*)g_bufA;

#pragma unroll
    for (int j = 0; j < 4; ++j) {
        int col = cg * 32 + j * 8 + ((lane & 3) << 1);
        float2 bb = __ldg((const float2*)(b + col));
        if (mlo < n) {
            long long idx = (long long)mlo * D + col;
            *(float2*)(out + idx) = make_float2(fmaf(c0, acc[j][0], bb.x),
                                                fmaf(c0, acc[j][1], bb.y));
            h0[idx >> 1] = __floats2half2_rn(acc[j][0], acc[j][1]);
        }
        if (mhi < n) {
            long long idx = (long long)mhi * D + col;
            *(float2*)(out + idx) = make_float2(fmaf(c0, acc[j][2], bb.x),
                                                fmaf(c0, acc[j][3], bb.y));
            h0[idx >> 1] = __floats2half2_rn(acc[j][2], acc[j][3]);
        }
    }
}

// ================= LAUNCH 3: fused scan + write + scatter ===================
// 1024-thr blocks, one element per thread (grid = ceil(N/1024) = 49 blocks).
// phases: block partial sums -> bar -> block0 scans partials -> bar ->
//         write rowptr/cursor/dinv -> bar -> scatter (grid-stride over E)
__global__ void __launch_bounds__(1024) k_scan_all(
    const void* __restrict__ ei, int N, int E)
{
    __shared__ int ws[32];
    __shared__ int sp[SBMAX];
    int tid  = threadIdx.x;
    int bid  = blockIdx.x;
    int lane = tid & 31, wid = tid >> 5;
    int i = bid * 1024 + tid;
    int d = (i < N) ? g_deg[i] : 0;

    // phase A: block partial sum
    {
        int v = d;
#pragma unroll
        for (int off = 16; off > 0; off >>= 1)
            v += __shfl_down_sync(0xffffffffu, v, off);
        if (lane == 0) ws[wid] = v;
        __syncthreads();
        if (wid == 0) {
            int s = (lane < 32) ? ws[lane] : 0;
#pragma unroll
            for (int off = 16; off > 0; off >>= 1)
                s += __shfl_down_sync(0xffffffffu, s, off);
            if (lane == 0) g_bsum[bid] = s;
        }
    }
    gridbar();

    // phase B: block 0 exclusive-scans the partials (nb <= 49, serial fine)
    if (bid == 0 && tid == 0) {
        int nb = gridDim.x;
        int run = 0;
        for (int j = 0; j < nb; ++j) { int v = g_bsum[j]; g_bsum[j] = run; run += v; }
    }
    gridbar();

    // phase C: intra-block scan + write rowptr/cursor/dinv
    {
        int v = d;
#pragma unroll
        for (int off = 1; off < 32; off <<= 1) {
            int t = __shfl_up_sync(0xffffffffu, v, off);
            if (lane >= off) v += t;
        }
        __syncthreads();            // ws reuse
        if (lane == 31) ws[wid] = v;
        __syncthreads();
        if (wid == 0) {
            int wv = ws[lane];
#pragma unroll
            for (int off = 1; off < 32; off <<= 1) {
                int t = __shfl_up_sync(0xffffffffu, wv, off);
                if (lane >= off) wv += t;
            }
            ws[lane] = wv;
        }
        __syncthreads();

        int excl = v - d + (wid ? ws[wid - 1] : 0) + g_bsum[bid];
        if (i < N) {
            g_rowptr[i] = excl;
            g_cursor[i] = excl;
            g_dinv[i]   = rsqrtf((float)d + 1.0f);
            if (i == N - 1) g_rowptr[N] = excl + d;
        }
    }
    gridbar();

    // phase D: scatter edges into CSR (grid-stride)
    (void)sp;
    int gt   = bid * 1024 + tid;
    int step = gridDim.x * 1024;
    for (int e = gt; e < E; e += step) {
        int src = load_idx(ei, e);
        int dst = load_idx(ei, (long long)E + e);
        int pos = atomicAdd(&g_cursor[dst], 1);
        g_csr[pos] = make_int2(src, __float_as_int(g_dinv[src]));
    }
}

// ================= LAUNCH 4..13: one diffusion hop (R13, known good) ========
__global__ void __launch_bounds__(128) k_hop(
    int flip, int k, int n, float4* __restrict__ out, int do_out, int write_h)
{
    int gw = (blockIdx.x * blockDim.x + threadIdx.x) >> 5;
    if (gw >= n) return;
    int lane = threadIdx.x & 31;

    const uint2* __restrict__ hin  = flip ? (const uint2*)g_bufB : (const uint2*)g_bufA;
    uint2*       __restrict__ hout = flip ? (uint2*)g_bufA       : (uint2*)g_bufB;

    int beg = g_rowptr[gw];
    int end = g_rowptr[gw + 1];

    uint2 ps = __ldg(&hin[gw * DH2 + lane]);

    float4 acc  = make_float4(0.f,0.f,0.f,0.f);
    float4 acc2 = make_float4(0.f,0.f,0.f,0.f);

    int e = beg;
    for (; e + 8 <= end; e += 8) {
        int2 c0 = __ldg(&g_csr[e + 0]);
        int2 c1 = __ldg(&g_csr[e + 1]);
        int2 c2 = __ldg(&g_csr[e + 2]);
        int2 c3 = __ldg(&g_csr[e + 3]);
        int2 c4 = __ldg(&g_csr[e + 4]);
        int2 c5 = __ldg(&g_csr[e + 5]);
        int2 c6 = __ldg(&g_csr[e + 6]);
        int2 c7 = __ldg(&g_csr[e + 7]);
        uint2 p0 = __ldg(&hin[c0.x * DH2 + lane]);
        uint2 p1 = __ldg(&hin[c1.x * DH2 + lane]);
        uint2 p2 = __ldg(&hin[c2.x * DH2 + lane]);
        uint2 p3 = __ldg(&hin[c3.x * DH2 + lane]);
        uint2 p4 = __ldg(&hin[c4.x * DH2 + lane]);
        uint2 p5 = __ldg(&hin[c5.x * DH2 + lane]);
        uint2 p6 = __ldg(&hin[c6.x * DH2 + lane]);
        uint2 p7 = __ldg(&hin[c7.x * DH2 + lane]);
        fma_h4(p0, __int_as_float(c0.y), acc);
        fma_h4(p1, __int_as_float(c1.y), acc2);
        fma_h4(p2, __int_as_float(c2.y), acc);
        fma_h4(p3, __int_as_float(c3.y), acc2);
        fma_h4(p4, __int_as_float(c4.y), acc);
        fma_h4(p5, __int_as_float(c5.y), acc2);
        fma_h4(p6, __int_as_float(c6.y), acc);
        fma_h4(p7, __int_as_float(c7.y), acc2);
    }
    for (; e + 4 <= end; e += 4) {
        int2 c0 = __ldg(&g_csr[e + 0]);
        int2 c1 = __ldg(&g_csr[e + 1]);
        int2 c2 = __ldg(&g_csr[e + 2]);
        int2 c3 = __ldg(&g_csr[e + 3]);
        uint2 p0 = __ldg(&hin[c0.x * DH2 + lane]);
        uint2 p1 = __ldg(&hin[c1.x * DH2 + lane]);
        uint2 p2 = __ldg(&hin[c2.x * DH2 + lane]);
        uint2 p3 = __ldg(&hin[c3.x * DH2 + lane]);
        fma_h4(p0, __int_as_float(c0.y), acc);
        fma_h4(p1, __int_as_float(c1.y), acc2);
        fma_h4(p2, __int_as_float(c2.y), acc);
        fma_h4(p3, __int_as_float(c3.y), acc2);
    }
    for (; e < end; ++e) {
        int2 c = __ldg(&g_csr[e]);
        uint2 p = __ldg(&hin[c.x * DH2 + lane]);
        fma_h4(p, __int_as_float(c.y), acc);
    }

    float di  = g_dinv[gw];
    float di2 = di * di;
    float2 slo = __half22float2(*(const __half2*)&ps.x);
    float2 shi = __half22float2(*(const __half2*)&ps.y);

    float4 r;
    r.x = fmaf(di, acc.x + acc2.x, di2 * slo.x);
    r.y = fmaf(di, acc.y + acc2.y, di2 * slo.y);
    r.z = fmaf(di, acc.z + acc2.z, di2 * shi.x);
    r.w = fmaf(di, acc.w + acc2.w, di2 * shi.y);

    int idx = gw * DH2 + lane;
    if (write_h) hout[idx] = pack_h4(r);

    if (do_out) {
        float cp = g_coeff[k - 1];
        float c  = g_coeff[k];
        float4 o = out[idx];
        o.x = fmaf(cp, slo.x, o.x);
        o.y = fmaf(cp, slo.y, o.y);
        o.z = fmaf(cp, shi.x, o.z);
        o.w = fmaf(cp, shi.y, o.w);
        o.x = fmaf(c, r.x, o.x);
        o.y = fmaf(c, r.y, o.y);
        o.z = fmaf(c, r.z, o.z);
        o.w = fmaf(c, r.w, o.w);
        out[idx] = o;
    }
}

// ---------------- launch ------------------------------------------------------
extern "C" void kernel_launch(void* const* d_in, const int* in_sizes, int n_in,
                              void* d_out, int out_size) {
    const float* x  = (const float*)d_in[0];
    const void*  ei = d_in[1];
    const float* t  = (const float*)d_in[2];
    const float* W  = (const float*)d_in[3];
    const float* b  = (const float*)d_in[4];
    float* out = (float*)d_out;

    int N = in_sizes[0] / D;
    int E = in_sizes[1] / 2;

    int ngemm = (N + BM - 1) / BM;      // 1563
    int nhist = 256;                     // 65536 threads grid-stride over E
    int nscan = (N + 1023) / 1024;       // 49
    if (nscan > SBMAX) nscan = SBMAX;    // (N<=NMAX keeps this untaken)

    k_pre<<<(N + 255) / 256, 256>>>(ei, t, N);
    k_combo<<<ngemm + nhist, 256>>>(x, W, b, ei, out, N, E, ngemm, nhist);
    k_scan_all<<<nscan, 1024>>>(ei, N, E);

    int hop_blocks = (N + 3) / 4;        // 4 warps per block, warp per node
    for (int k = 1; k <= KHOPS; ++k) {
        int flip    = (k - 1) & 1;
        int do_out  = (k & 1) == 0;
        int write_h = (k < KHOPS);
        k_hop<<<hop_blocks, 128>>>(flip, k, N, (float4*)out, do_out, write_h);
    }
}

// round 16
// speedup vs baseline: 1.0641x; 1.0641x over previous
#include <cuda_runtime.h>
#include <cuda_fp16.h>

#define D      128
#define D4     32
#define DH2    32
#define KHOPS  10
#define SCAN_T 1024
#define BM     32

static const int NMAX = 50000;
static const int EMAX = 625000;
static const int BMAX = 64;

// ---------------- scratch (device globals; no allocation allowed) ----------
__device__ __half g_bufA[NMAX * D];     // h ping (fp16 state)
__device__ __half g_bufB[NMAX * D];     // h pong
__device__ int    g_deg[NMAX];
__device__ int    g_rowptr[NMAX + 1];
__device__ int    g_cursor[NMAX];
__device__ float  g_dinv[NMAX];
__device__ int2   g_csr[EMAX];          // {src, bitcast(dinv[src])}
__device__ __half g_Wh[D * D];          // W in fp16, [o][k]
__device__ float  g_coeff[KHOPS + 1];
__device__ int    g_is64;
__device__ int    g_bsum[BMAX];

// ---------------- fused setup: W->fp16 + deg zero + detect + coeffs --------
__global__ void k_setup(const void* __restrict__ ei,
                        const float* __restrict__ t_ptr,
                        const float* __restrict__ W, int n) {
    int i = blockIdx.x * blockDim.x + threadIdx.x;
    if (i < D * D) g_Wh[i] = __float2half(W[i]);
    if (i < n)     g_deg[i] = 0;
    if (i == 0) {
        const int* a = (const int*)ei;
        int is64 = 1;
#pragma unroll
        for (int j = 1; j < 32; j += 2)
            if (a[j] != 0) is64 = 0;
        g_is64 = is64;
        float t = *t_ptr;
        float cc = expf(-t);
        g_coeff[0] = cc;
        for (int k = 1; k <= KHOPS; ++k) { cc = cc * t / (float)k; g_coeff[k] = cc; }
    }
}

__device__ __forceinline__ int load_idx(const void* ei, long long pos) {
    if (g_is64) return (int)((const long long*)ei)[pos];
    return ((const int*)ei)[pos];
}

__global__ void k_hist(const void* __restrict__ ei, int E) {
    int e = blockIdx.x * blockDim.x + threadIdx.x;
    if (e < E) {
        int dst = load_idx(ei, (long long)E + e);
        atomicAdd(&g_deg[dst], 1);
    }
}

// ---------------- 3-phase coalesced scan -------------------------------------
__global__ void __launch_bounds__(SCAN_T) k_blocksum(int n) {
    int i = blockIdx.x * SCAN_T + threadIdx.x;
    int v = (i < n) ? g_deg[i] : 0;
    int lane = threadIdx.x & 31, wid = threadIdx.x >> 5;
#pragma unroll
    for (int off = 16; off > 0; off >>= 1)
        v += __shfl_down_sync(0xffffffffu, v, off);
    __shared__ int ws[32];
    if (lane == 0) ws[wid] = v;
    __syncthreads();
    if (wid == 0) {
        int s = (lane < SCAN_T / 32) ? ws[lane] : 0;
#pragma unroll
        for (int off = 16; off > 0; off >>= 1)
            s += __shfl_down_sync(0xffffffffu, s, off);
        if (lane == 0) g_bsum[blockIdx.x] = s;
    }
}

__global__ void k_scanb(int nb) {
    int lane = threadIdx.x;
    __shared__ int s[BMAX];
    s[lane] = (lane < nb) ? g_bsum[lane] : 0;
    __syncthreads();
    if (lane == 0) {
        int run = 0;
        for (int j = 0; j < nb; ++j) { int d = s[j]; s[j] = run; run += d; }
    }
    __syncthreads();
    g_bsum[lane] = s[lane];
}

__global__ void __launch_bounds__(SCAN_T) k_write(int n) {
    int i = blockIdx.x * SCAN_T + threadIdx.x;
    int d = (i < n) ? g_deg[i] : 0;
    int lane = threadIdx.x & 31, wid = threadIdx.x >> 5;

    int v = d;
#pragma unroll
    for (int off = 1; off < 32; off <<= 1) {
        int t = __shfl_up_sync(0xffffffffu, v, off);
        if (lane >= off) v += t;
    }
    __shared__ int ws[32];
    if (lane == 31) ws[wid] = v;
    __syncthreads();
    if (wid == 0) {
        int wv = ws[lane];
#pragma unroll
        for (int off = 1; off < 32; off <<= 1) {
            int t = __shfl_up_sync(0xffffffffu, wv, off);
            if (lane >= off) wv += t;
        }
        ws[lane] = wv;
    }
    __syncthreads();

    int excl = v - d + (wid ? ws[wid - 1] : 0) + g_bsum[blockIdx.x];
    if (i < n) {
        g_rowptr[i] = excl;
        g_cursor[i] = excl;
        g_dinv[i]   = rsqrtf((float)d + 1.0f);
        if (i == n - 1) g_rowptr[n] = excl + d;
    }
}

__global__ void k_scatter(const void* __restrict__ ei, int E) {
    int e = blockIdx.x * blockDim.x + threadIdx.x;
    if (e < E) {
        int src = load_idx(ei, e);
        int dst = load_idx(ei, (long long)E + e);
        int pos = atomicAdd(&g_cursor[dst], 1);
        g_csr[pos] = make_int2(src, __float_as_int(g_dinv[src]));
    }
}

// ------------- fp16 helpers --------------------------------------------------
__device__ __forceinline__ void fma_h4(uint2 p, float w, float4& a) {
    float2 lo = __half22float2(*(const __half2*)&p.x);
    float2 hi = __half22float2(*(const __half2*)&p.y);
    a.x = fmaf(w, lo.x, a.x); a.y = fmaf(w, lo.y, a.y);
    a.z = fmaf(w, hi.x, a.z); a.w = fmaf(w, hi.y, a.w);
}
__device__ __forceinline__ uint2 pack_h4(float4 r) {
    __half2 lo = __floats2half2_rn(r.x, r.y);
    __half2 hi = __floats2half2_rn(r.z, r.w);
    uint2 p;
    p.x = *(const unsigned int*)&lo;
    p.y = *(const unsigned int*)&hi;
    return p;
}
__device__ __forceinline__ unsigned int smem_u32(const void* p) {
    return (unsigned int)__cvta_generic_to_shared(p);
}

// ---------------- HMMA GEMM (known good) -------------------------------------
__global__ void __launch_bounds__(256) k_gemm_mma(
    const float* __restrict__ x, const float* __restrict__ b,
    float* __restrict__ out, int n)
{
    __shared__ __align__(16) __half sA[BM][D + 8];
    __shared__ __align__(16) __half sW[D][D + 8];

    int tid  = threadIdx.x;
    int warp = tid >> 5;
    int lane = tid & 31;
    int rowb = blockIdx.x * BM;
    int rows = n - rowb; if (rows > BM) rows = BM;

    const uint4* Wh4 = (const uint4*)g_Wh;
#pragma unroll
    for (int i = tid; i < D * (D / 8); i += 256) {
        int r = i >> 4, c = i & 15;
        *(uint4*)&sW[r][c * 8] = __ldg(&Wh4[r * 16 + c]);
    }
    const float4* x4 = (const float4*)(x + (long long)rowb * D);
    for (int i = tid; i < rows * D4; i += 256) {
        int r = i >> 5, c = i & 31;
        float4 v = x4[i];
        *(half2*)&sA[r][c * 4]     = __floats2half2_rn(v.x, v.y);
        *(half2*)&sA[r][c * 4 + 2] = __floats2half2_rn(v.z, v.w);
    }
    __syncthreads();

    int rg = warp & 1, cg = warp >> 1;
    int r0 = rg * 16;

    float acc[4][4];
#pragma unroll
    for (int j = 0; j < 4; ++j)
#pragma unroll
        for (int q = 0; q < 4; ++q) acc[j][q] = 0.f;

    int aRow = r0 + (lane & 15);
    int aCol = (lane >> 4) << 3;
    int bN = (lane & 7) + ((lane >> 4) << 3);
    int bK = ((lane >> 3) & 1) << 3;

#pragma unroll
    for (int k0 = 0; k0 < D; k0 += 16) {
        unsigned int a0, a1, a2, a3;
        unsigned int aAddr = smem_u32(&sA[aRow][k0 + aCol]);
        asm volatile("ldmatrix.sync.aligned.m8n8.x4.shared.b16 {%0,%1,%2,%3}, [%4];"
                     : "=r"(a0), "=r"(a1), "=r"(a2), "=r"(a3) : "r"(aAddr));
#pragma unroll
        for (int h16 = 0; h16 < 2; ++h16) {
            int nbase = cg * 32 + h16 * 16;
            unsigned int b0, b1, b2, b3;
            unsigned int bAddr = smem_u32(&sW[nbase + bN][k0 + bK]);
            asm volatile("ldmatrix.sync.aligned.m8n8.x4.shared.b16 {%0,%1,%2,%3}, [%4];"
                         : "=r"(b0), "=r"(b1), "=r"(b2), "=r"(b3) : "r"(bAddr));
            int j0 = h16 * 2;
            asm volatile("mma.sync.aligned.m16n8k16.row.col.f32.f16.f16.f32 "
                         "{%0,%1,%2,%3},{%4,%5,%6,%7},{%8,%9},{%0,%1,%2,%3};"
                         : "+f"(acc[j0][0]), "+f"(acc[j0][1]), "+f"(acc[j0][2]), "+f"(acc[j0][3])
                         : "r"(a0), "r"(a1), "r"(a2), "r"(a3), "r"(b0), "r"(b1));
            asm volatile("mma.sync.aligned.m16n8k16.row.col.f32.f16.f16.f32 "
                         "{%0,%1,%2,%3},{%4,%5,%6,%7},{%8,%9},{%0,%1,%2,%3};"
                         : "+f"(acc[j0+1][0]), "+f"(acc[j0+1][1]), "+f"(acc[j0+1][2]), "+f"(acc[j0+1][3])
                         : "r"(a0), "r"(a1), "r"(a2), "r"(a3), "r"(b2), "r"(b3));
        }
    }

    float c0 = g_coeff[0];
    int mlo = rowb + r0 + (lane >> 2);
    int mhi = mlo + 8;
    __half2* h0 = (__half2*)g_bufA;

#pragma unroll
    for (int j = 0; j < 4; ++j) {
        int col = cg * 32 + j * 8 + ((lane & 3) << 1);
        float2 bb = __ldg((const float2*)(b + col));
        if (mlo < n) {
            long long idx = (long long)mlo * D + col;
            *(float2*)(out + idx) = make_float2(fmaf(c0, acc[j][0], bb.x),
                                                fmaf(c0, acc[j][1], bb.y));
            h0[idx >> 1] = __floats2half2_rn(acc[j][0], acc[j][1]);
        }
        if (mhi < n) {
            long long idx = (long long)mhi * D + col;
            *(float2*)(out + idx) = make_float2(fmaf(c0, acc[j][2], bb.x),
                                                fmaf(c0, acc[j][3], bb.y));
            h0[idx >> 1] = __floats2half2_rn(acc[j][2], acc[j][3]);
        }
    }
}

// ---------------- one diffusion hop (R13 body, 64-thread blocks) -------------
__global__ void __launch_bounds__(64) k_hop(
    int flip, int k, int n, float4* __restrict__ out, int do_out, int write_h)
{
    int gw = (blockIdx.x * blockDim.x + threadIdx.x) >> 5;
    if (gw >= n) return;
    int lane = threadIdx.x & 31;

    const uint2* __restrict__ hin  = flip ? (const uint2*)g_bufB : (const uint2*)g_bufA;
    uint2*       __restrict__ hout = flip ? (uint2*)g_bufA       : (uint2*)g_bufB;

    int beg = g_rowptr[gw];
    int end = g_rowptr[gw + 1];

    uint2 ps = __ldg(&hin[gw * DH2 + lane]);

    float4 acc  = make_float4(0.f,0.f,0.f,0.f);
    float4 acc2 = make_float4(0.f,0.f,0.f,0.f);

    int e = beg;
    for (; e + 8 <= end; e += 8) {
        int2 c0 = __ldg(&g_csr[e + 0]);
        int2 c1 = __ldg(&g_csr[e + 1]);
        int2 c2 = __ldg(&g_csr[e + 2]);
        int2 c3 = __ldg(&g_csr[e + 3]);
        int2 c4 = __ldg(&g_csr[e + 4]);
        int2 c5 = __ldg(&g_csr[e + 5]);
        int2 c6 = __ldg(&g_csr[e + 6]);
        int2 c7 = __ldg(&g_csr[e + 7]);
        uint2 p0 = __ldg(&hin[c0.x * DH2 + lane]);
        uint2 p1 = __ldg(&hin[c1.x * DH2 + lane]);
        uint2 p2 = __ldg(&hin[c2.x * DH2 + lane]);
        uint2 p3 = __ldg(&hin[c3.x * DH2 + lane]);
        uint2 p4 = __ldg(&hin[c4.x * DH2 + lane]);
        uint2 p5 = __ldg(&hin[c5.x * DH2 + lane]);
        uint2 p6 = __ldg(&hin[c6.x * DH2 + lane]);
        uint2 p7 = __ldg(&hin[c7.x * DH2 + lane]);
        fma_h4(p0, __int_as_float(c0.y), acc);
        fma_h4(p1, __int_as_float(c1.y), acc2);
        fma_h4(p2, __int_as_float(c2.y), acc);
        fma_h4(p3, __int_as_float(c3.y), acc2);
        fma_h4(p4, __int_as_float(c4.y), acc);
        fma_h4(p5, __int_as_float(c5.y), acc2);
        fma_h4(p6, __int_as_float(c6.y), acc);
        fma_h4(p7, __int_as_float(c7.y), acc2);
    }
    for (; e + 4 <= end; e += 4) {
        int2 c0 = __ldg(&g_csr[e + 0]);
        int2 c1 = __ldg(&g_csr[e + 1]);
        int2 c2 = __ldg(&g_csr[e + 2]);
        int2 c3 = __ldg(&g_csr[e + 3]);
        uint2 p0 = __ldg(&hin[c0.x * DH2 + lane]);
        uint2 p1 = __ldg(&hin[c1.x * DH2 + lane]);
        uint2 p2 = __ldg(&hin[c2.x * DH2 + lane]);
        uint2 p3 = __ldg(&hin[c3.x * DH2 + lane]);
        fma_h4(p0, __int_as_float(c0.y), acc);
        fma_h4(p1, __int_as_float(c1.y), acc2);
        fma_h4(p2, __int_as_float(c2.y), acc);
        fma_h4(p3, __int_as_float(c3.y), acc2);
    }
    for (; e < end; ++e) {
        int2 c = __ldg(&g_csr[e]);
        uint2 p = __ldg(&hin[c.x * DH2 + lane]);
        fma_h4(p, __int_as_float(c.y), acc);
    }

    float di  = g_dinv[gw];
    float di2 = di * di;
    float2 slo = __half22float2(*(const __half2*)&ps.x);
    float2 shi = __half22float2(*(const __half2*)&ps.y);

    float4 r;
    r.x = fmaf(di, acc.x + acc2.x, di2 * slo.x);
    r.y = fmaf(di, acc.y + acc2.y, di2 * slo.y);
    r.z = fmaf(di, acc.z + acc2.z, di2 * shi.x);
    r.w = fmaf(di, acc.w + acc2.w, di2 * shi.y);

    int idx = gw * DH2 + lane;
    if (write_h) hout[idx] = pack_h4(r);

    if (do_out) {
        float cp = g_coeff[k - 1];
        float c  = g_coeff[k];
        float4 o = out[idx];
        o.x = fmaf(cp, slo.x, o.x);
        o.y = fmaf(cp, slo.y, o.y);
        o.z = fmaf(cp, shi.x, o.z);
        o.w = fmaf(cp, shi.y, o.w);
        o.x = fmaf(c, r.x, o.x);
        o.y = fmaf(c, r.y, o.y);
        o.z = fmaf(c, r.z, o.z);
        o.w = fmaf(c, r.w, o.w);
        out[idx] = o;
    }
}

// ---------------- launch ------------------------------------------------------
extern "C" void kernel_launch(void* const* d_in, const int* in_sizes, int n_in,
                              void* d_out, int out_size) {
    const float* x  = (const float*)d_in[0];
    const void*  ei = d_in[1];
    const float* t  = (const float*)d_in[2];
    const float* W  = (const float*)d_in[3];
    const float* b  = (const float*)d_in[4];
    float* out = (float*)d_out;

    int N = in_sizes[0] / D;
    int E = in_sizes[1] / 2;
    int nb = (N + SCAN_T - 1) / SCAN_T;
    int setup_elems = (N > D * D) ? N : D * D;

    k_setup<<<(setup_elems + 255) / 256, 256>>>(ei, t, W, N);
    k_hist<<<(E + 255) / 256, 256>>>(ei, E);
    k_blocksum<<<nb, SCAN_T>>>(N);
    k_scanb<<<1, BMAX>>>(nb);
    k_write<<<nb, SCAN_T>>>(N);
    k_scatter<<<(E + 255) / 256, 256>>>(ei, E);
    k_gemm_mma<<<(N + BM - 1) / BM, 256>>>(x, b, out, N);

    int hop_blocks = (N + 1) / 2;   // 2 warps per block, warp per node
    for (int k = 1; k <= KHOPS; ++k) {
        int flip    = (k - 1) & 1;
        int do_out  = (k & 1) == 0;
        int write_h = (k < KHOPS);
        k_hop<<<hop_blocks, 64>>>(flip, k, N, (float4*)out, do_out, write_h);
    }
}

// round 17
// speedup vs baseline: 1.0659x; 1.0017x over previous
#include <cuda_runtime.h>
#include <cuda_fp16.h>

#define D      128
#define D4     32
#define DH2    32
#define KHOPS  10
#define SCAN_T 1024
#define BM     32

static const int NMAX = 50000;
static const int EMAX = 625000;
static const int BMAX = 64;

// ---------------- scratch (device globals; no allocation allowed) ----------
__device__ __half g_bufA[NMAX * D];     // h ping (fp16 state)
__device__ __half g_bufB[NMAX * D];     // h pong
__device__ int    g_deg[NMAX];
__device__ int    g_rowptr[NMAX + 1];
__device__ int    g_cursor[NMAX];
__device__ float  g_dinv[NMAX];
__device__ int2   g_csr[EMAX];          // {src, bitcast(dinv[src])}
__device__ __half g_Wh[D * D];          // W in fp16, [o][k]
__device__ float  g_coeff[KHOPS + 1];
__device__ int    g_is64;
__device__ int    g_bsum[BMAX];

// ---------------- fused setup: W->fp16 + deg zero + detect + coeffs --------
__global__ void k_setup(const void* __restrict__ ei,
                        const float* __restrict__ t_ptr,
                        const float* __restrict__ W, int n) {
    int i = blockIdx.x * blockDim.x + threadIdx.x;
    if (i < D * D) g_Wh[i] = __float2half(W[i]);
    if (i < n)     g_deg[i] = 0;
    if (i == 0) {
        const int* a = (const int*)ei;
        int is64 = 1;
#pragma unroll
        for (int j = 1; j < 32; j += 2)
            if (a[j] != 0) is64 = 0;
        g_is64 = is64;
        float t = *t_ptr;
        float cc = expf(-t);
        g_coeff[0] = cc;
        for (int k = 1; k <= KHOPS; ++k) { cc = cc * t / (float)k; g_coeff[k] = cc; }
    }
}

__device__ __forceinline__ int load_idx(const void* ei, long long pos) {
    if (g_is64) return (int)((const long long*)ei)[pos];
    return ((const int*)ei)[pos];
}

__global__ void k_hist(const void* __restrict__ ei, int E) {
    int e = blockIdx.x * blockDim.x + threadIdx.x;
    if (e < E) {
        int dst = load_idx(ei, (long long)E + e);
        atomicAdd(&g_deg[dst], 1);
    }
}

// ---------------- scan: blocksum then write (scanb folded into write) -------
__global__ void __launch_bounds__(SCAN_T) k_blocksum(int n) {
    int i = blockIdx.x * SCAN_T + threadIdx.x;
    int v = (i < n) ? g_deg[i] : 0;
    int lane = threadIdx.x & 31, wid = threadIdx.x >> 5;
#pragma unroll
    for (int off = 16; off > 0; off >>= 1)
        v += __shfl_down_sync(0xffffffffu, v, off);
    __shared__ int ws[32];
    if (lane == 0) ws[wid] = v;
    __syncthreads();
    if (wid == 0) {
        int s = (lane < SCAN_T / 32) ? ws[lane] : 0;
#pragma unroll
        for (int off = 16; off > 0; off >>= 1)
            s += __shfl_down_sync(0xffffffffu, s, off);
        if (lane == 0) g_bsum[blockIdx.x] = s;
    }
}

// Each block computes its own carry = sum(g_bsum[0..bid)) inline (<=64 ints),
// then intra-block scan + coalesced writes of rowptr / cursor / dinv.
__global__ void __launch_bounds__(SCAN_T) k_write(int n) {
    int i = blockIdx.x * SCAN_T + threadIdx.x;
    int d = (i < n) ? g_deg[i] : 0;
    int lane = threadIdx.x & 31, wid = threadIdx.x >> 5;
    __shared__ int ws[32];
    __shared__ int s_carry;

    // warp 0: carry = sum of partials before this block (bid <= 49 < 64)
    if (wid == 0) {
        int c = 0;
        for (int j = lane; j < (int)blockIdx.x; j += 32)
            c += g_bsum[j];
#pragma unroll
        for (int off = 16; off > 0; off >>= 1)
            c += __shfl_down_sync(0xffffffffu, c, off);
        if (lane == 0) s_carry = c;
    }

    int v = d;
#pragma unroll
    for (int off = 1; off < 32; off <<= 1) {
        int t = __shfl_up_sync(0xffffffffu, v, off);
        if (lane >= off) v += t;
    }
    if (lane == 31) ws[wid] = v;
    __syncthreads();
    if (wid == 0) {
        int wv = ws[lane];
#pragma unroll
        for (int off = 1; off < 32; off <<= 1) {
            int t = __shfl_up_sync(0xffffffffu, wv, off);
            if (lane >= off) wv += t;
        }
        ws[lane] = wv;
    }
    __syncthreads();

    int excl = v - d + (wid ? ws[wid - 1] : 0) + s_carry;
    if (i < n) {
        g_rowptr[i] = excl;
        g_cursor[i] = excl;
        g_dinv[i]   = rsqrtf((float)d + 1.0f);
        if (i == n - 1) g_rowptr[n] = excl + d;
    }
}

__global__ void k_scatter(const void* __restrict__ ei, int E) {
    int e = blockIdx.x * blockDim.x + threadIdx.x;
    if (e < E) {
        int src = load_idx(ei, e);
        int dst = load_idx(ei, (long long)E + e);
        int pos = atomicAdd(&g_cursor[dst], 1);
        g_csr[pos] = make_int2(src, __float_as_int(g_dinv[src]));
    }
}

// ------------- fp16 helpers --------------------------------------------------
__device__ __forceinline__ void fma_h4(uint2 p, float w, float4& a) {
    float2 lo = __half22float2(*(const __half2*)&p.x);
    float2 hi = __half22float2(*(const __half2*)&p.y);
    a.x = fmaf(w, lo.x, a.x); a.y = fmaf(w, lo.y, a.y);
    a.z = fmaf(w, hi.x, a.z); a.w = fmaf(w, hi.y, a.w);
}
__device__ __forceinline__ uint2 pack_h4(float4 r) {
    __half2 lo = __floats2half2_rn(r.x, r.y);
    __half2 hi = __floats2half2_rn(r.z, r.w);
    uint2 p;
    p.x = *(const unsigned int*)&lo;
    p.y = *(const unsigned int*)&hi;
    return p;
}
__device__ __forceinline__ unsigned int smem_u32(const void* p) {
    return (unsigned int)__cvta_generic_to_shared(p);
}

// ---------------- HMMA GEMM (known good) -------------------------------------
__global__ void __launch_bounds__(256) k_gemm_mma(
    const float* __restrict__ x, const float* __restrict__ b,
    float* __restrict__ out, int n)
{
    __shared__ __align__(16) __half sA[BM][D + 8];
    __shared__ __align__(16) __half sW[D][D + 8];

    int tid  = threadIdx.x;
    int warp = tid >> 5;
    int lane = tid & 31;
    int rowb = blockIdx.x * BM;
    int rows = n - rowb; if (rows > BM) rows = BM;

    const uint4* Wh4 = (const uint4*)g_Wh;
#pragma unroll
    for (int i = tid; i < D * (D / 8); i += 256) {
        int r = i >> 4, c = i & 15;
        *(uint4*)&sW[r][c * 8] = __ldg(&Wh4[r * 16 + c]);
    }
    const float4* x4 = (const float4*)(x + (long long)rowb * D);
    for (int i = tid; i < rows * D4; i += 256) {
        int r = i >> 5, c = i & 31;
        float4 v = x4[i];
        *(half2*)&sA[r][c * 4]     = __floats2half2_rn(v.x, v.y);
        *(half2*)&sA[r][c * 4 + 2] = __floats2half2_rn(v.z, v.w);
    }
    __syncthreads();

    int rg = warp & 1, cg = warp >> 1;
    int r0 = rg * 16;

    float acc[4][4];
#pragma unroll
    for (int j = 0; j < 4; ++j)
#pragma unroll
        for (int q = 0; q < 4; ++q) acc[j][q] = 0.f;

    int aRow = r0 + (lane & 15);
    int aCol = (lane >> 4) << 3;
    int bN = (lane & 7) + ((lane >> 4) << 3);
    int bK = ((lane >> 3) & 1) << 3;

#pragma unroll
    for (int k0 = 0; k0 < D; k0 += 16) {
        unsigned int a0, a1, a2, a3;
        unsigned int aAddr = smem_u32(&sA[aRow][k0 + aCol]);
        asm volatile("ldmatrix.sync.aligned.m8n8.x4.shared.b16 {%0,%1,%2,%3}, [%4];"
                     : "=r"(a0), "=r"(a1), "=r"(a2), "=r"(a3) : "r"(aAddr));
#pragma unroll
        for (int h16 = 0; h16 < 2; ++h16) {
            int nbase = cg * 32 + h16 * 16;
            unsigned int b0, b1, b2, b3;
            unsigned int bAddr = smem_u32(&sW[nbase + bN][k0 + bK]);
            asm volatile("ldmatrix.sync.aligned.m8n8.x4.shared.b16 {%0,%1,%2,%3}, [%4];"
                         : "=r"(b0), "=r"(b1), "=r"(b2), "=r"(b3) : "r"(bAddr));
            int j0 = h16 * 2;
            asm volatile("mma.sync.aligned.m16n8k16.row.col.f32.f16.f16.f32 "
                         "{%0,%1,%2,%3},{%4,%5,%6,%7},{%8,%9},{%0,%1,%2,%3};"
                         : "+f"(acc[j0][0]), "+f"(acc[j0][1]), "+f"(acc[j0][2]), "+f"(acc[j0][3])
                         : "r"(a0), "r"(a1), "r"(a2), "r"(a3), "r"(b0), "r"(b1));
            asm volatile("mma.sync.aligned.m16n8k16.row.col.f32.f16.f16.f32 "
                         "{%0,%1,%2,%3},{%4,%5,%6,%7},{%8,%9},{%0,%1,%2,%3};"
                         : "+f"(acc[j0+1][0]), "+f"(acc[j0+1][1]), "+f"(acc[j0+1][2]), "+f"(acc[j0+1][3])
                         : "r"(a0), "r"(a1), "r"(a2), "r"(a3), "r"(b2), "r"(b3));
        }
    }

    float c0 = g_coeff[0];
    int mlo = rowb + r0 + (lane >> 2);
    int mhi = mlo + 8;
    __half2* h0 = (__half2*)g_bufA;

#pragma unroll
    for (int j = 0; j < 4; ++j) {
        int col = cg * 32 + j * 8 + ((lane & 3) << 1);
        float2 bb = __ldg((const float2*)(b + col));
        if (mlo < n) {
            long long idx = (long long)mlo * D + col;
            *(float2*)(out + idx) = make_float2(fmaf(c0, acc[j][0], bb.x),
                                                fmaf(c0, acc[j][1], bb.y));
            h0[idx >> 1] = __floats2half2_rn(acc[j][0], acc[j][1]);
        }
        if (mhi < n) {
            long long idx = (long long)mhi * D + col;
            *(float2*)(out + idx) = make_float2(fmaf(c0, acc[j][2], bb.x),
                                                fmaf(c0, acc[j][3], bb.y));
            h0[idx >> 1] = __floats2half2_rn(acc[j][2], acc[j][3]);
        }
    }
}

// ---------------- one diffusion hop (64-thread blocks, known good) -----------
__global__ void __launch_bounds__(64) k_hop(
    int flip, int k, int n, float4* __restrict__ out, int do_out, int write_h)
{
    int gw = (blockIdx.x * blockDim.x + threadIdx.x) >> 5;
    if (gw >= n) return;
    int lane = threadIdx.x & 31;

    const uint2* __restrict__ hin  = flip ? (const uint2*)g_bufB : (const uint2*)g_bufA;
    uint2*       __restrict__ hout = flip ? (uint2*)g_bufA       : (uint2*)g_bufB;

    int beg = g_rowptr[gw];
    int end = g_rowptr[gw + 1];

    uint2 ps = __ldg(&hin[gw * DH2 + lane]);

    float4 acc  = make_float4(0.f,0.f,0.f,0.f);
    float4 acc2 = make_float4(0.f,0.f,0.f,0.f);

    int e = beg;
    for (; e + 8 <= end; e += 8) {
        int2 c0 = __ldg(&g_csr[e + 0]);
        int2 c1 = __ldg(&g_csr[e + 1]);
        int2 c2 = __ldg(&g_csr[e + 2]);
        int2 c3 = __ldg(&g_csr[e + 3]);
        int2 c4 = __ldg(&g_csr[e + 4]);
        int2 c5 = __ldg(&g_csr[e + 5]);
        int2 c6 = __ldg(&g_csr[e + 6]);
        int2 c7 = __ldg(&g_csr[e + 7]);
        uint2 p0 = __ldg(&hin[c0.x * DH2 + lane]);
        uint2 p1 = __ldg(&hin[c1.x * DH2 + lane]);
        uint2 p2 = __ldg(&hin[c2.x * DH2 + lane]);
        uint2 p3 = __ldg(&hin[c3.x * DH2 + lane]);
        uint2 p4 = __ldg(&hin[c4.x * DH2 + lane]);
        uint2 p5 = __ldg(&hin[c5.x * DH2 + lane]);
        uint2 p6 = __ldg(&hin[c6.x * DH2 + lane]);
        uint2 p7 = __ldg(&hin[c7.x * DH2 + lane]);
        fma_h4(p0, __int_as_float(c0.y), acc);
        fma_h4(p1, __int_as_float(c1.y), acc2);
        fma_h4(p2, __int_as_float(c2.y), acc);
        fma_h4(p3, __int_as_float(c3.y), acc2);
        fma_h4(p4, __int_as_float(c4.y), acc);
        fma_h4(p5, __int_as_float(c5.y), acc2);
        fma_h4(p6, __int_as_float(c6.y), acc);
        fma_h4(p7, __int_as_float(c7.y), acc2);
    }
    for (; e + 4 <= end; e += 4) {
        int2 c0 = __ldg(&g_csr[e + 0]);
        int2 c1 = __ldg(&g_csr[e + 1]);
        int2 c2 = __ldg(&g_csr[e + 2]);
        int2 c3 = __ldg(&g_csr[e + 3]);
        uint2 p0 = __ldg(&hin[c0.x * DH2 + lane]);
        uint2 p1 = __ldg(&hin[c1.x * DH2 + lane]);
        uint2 p2 = __ldg(&hin[c2.x * DH2 + lane]);
        uint2 p3 = __ldg(&hin[c3.x * DH2 + lane]);
        fma_h4(p0, __int_as_float(c0.y), acc);
        fma_h4(p1, __int_as_float(c1.y), acc2);
        fma_h4(p2, __int_as_float(c2.y), acc);
        fma_h4(p3, __int_as_float(c3.y), acc2);
    }
    for (; e < end; ++e) {
        int2 c = __ldg(&g_csr[e]);
        uint2 p = __ldg(&hin[c.x * DH2 + lane]);
        fma_h4(p, __int_as_float(c.y), acc);
    }

    float di  = g_dinv[gw];
    float di2 = di * di;
    float2 slo = __half22float2(*(const __half2*)&ps.x);
    float2 shi = __half22float2(*(const __half2*)&ps.y);

    float4 r;
    r.x = fmaf(di, acc.x + acc2.x, di2 * slo.x);
    r.y = fmaf(di, acc.y + acc2.y, di2 * slo.y);
    r.z = fmaf(di, acc.z + acc2.z, di2 * shi.x);
    r.w = fmaf(di, acc.w + acc2.w, di2 * shi.y);

    int idx = gw * DH2 + lane;
    if (write_h) hout[idx] = pack_h4(r);

    if (do_out) {
        float cp = g_coeff[k - 1];
        float c  = g_coeff[k];
        float4 o = out[idx];
        o.x = fmaf(cp, slo.x, o.x);
        o.y = fmaf(cp, slo.y, o.y);
        o.z = fmaf(cp, shi.x, o.z);
        o.w = fmaf(cp, shi.y, o.w);
        o.x = fmaf(c, r.x, o.x);
        o.y = fmaf(c, r.y, o.y);
        o.z = fmaf(c, r.z, o.z);
        o.w = fmaf(c, r.w, o.w);
        out[idx] = o;
    }
}

// ---------------- launch ------------------------------------------------------
extern "C" void kernel_launch(void* const* d_in, const int* in_sizes, int n_in,
                              void* d_out, int out_size) {
    const float* x  = (const float*)d_in[0];
    const void*  ei = d_in[1];
    const float* t  = (const float*)d_in[2];
    const float* W  = (const float*)d_in[3];
    const float* b  = (const float*)d_in[4];
    float* out = (float*)d_out;

    int N = in_sizes[0] / D;
    int E = in_sizes[1] / 2;
    int nb = (N + SCAN_T - 1) / SCAN_T;
    int setup_elems = (N > D * D) ? N : D * D;

    k_setup<<<(setup_elems + 255) / 256, 256>>>(ei, t, W, N);
    k_hist<<<(E + 255) / 256, 256>>>(ei, E);
    k_blocksum<<<nb, SCAN_T>>>(N);
    k_write<<<nb, SCAN_T>>>(N);
    k_scatter<<<(E + 255) / 256, 256>>>(ei, E);
    k_gemm_mma<<<(N + BM - 1) / BM, 256>>>(x, b, out, N);

    int hop_blocks = (N + 1) / 2;   // 2 warps per block, warp per node
    for (int k = 1; k <= KHOPS; ++k) {
        int flip    = (k - 1) & 1;
        int do_out  = (k & 1) == 0;
        int write_h = (k < KHOPS);
        k_hop<<<hop_blocks, 64>>>(flip, k, N, (float4*)out, do_out, write_h);
    }
}